// round 3
// baseline (speedup 1.0000x reference)
#include <cuda_runtime.h>
#include <math.h>

// Fixed problem shapes
#define Bv   16
#define Cc   256
#define Nn   64
#define NN   4096
#define Ss   128
#define EPSN 1e-12f
#define SCALE 10.0f
#define TPB  512     // 8 teams x 64 threads

typedef unsigned long long ull;

// Scratch: normalized sentence features + offsets
__device__ float g_sn1[Ss * Cc];
__device__ float g_sn2[Ss * Cc];
__device__ int   g_off[Bv + 1];

// Packed dual-fp32 FMA / ADD (Blackwell)
#define FFMA2(acc, a, bb) \
    asm("fma.rn.f32x2 %0, %1, %2, %0;" : "+l"(acc) : "l"(a), "l"(bb))
#define FADD2(dst, a, bb) \
    asm("add.rn.f32x2 %0, %1, %2;" : "=l"(dst) : "l"(a), "l"(bb))

__device__ __forceinline__ float f2lo(ull x) {
    return __uint_as_float((unsigned)(x & 0xffffffffu));
}
__device__ __forceinline__ float f2hi(ull x) {
    return __uint_as_float((unsigned)(x >> 32));
}

// ---------------------------------------------------------------------------
// Kernel 1: normalize sentence features (warp per row) + prefix offsets
// ---------------------------------------------------------------------------
__global__ void prep_kernel(const float* __restrict__ sf1,
                            const float* __restrict__ sf2,
                            const int*   __restrict__ nums) {
    if (blockIdx.x == 0 && threadIdx.x == 0) {
        int acc = 0;
        g_off[0] = 0;
        #pragma unroll
        for (int i = 0; i < Bv; i++) { acc += nums[i]; g_off[i + 1] = acc; }
    }
    int warp = threadIdx.x >> 5;
    int lane = threadIdx.x & 31;
    int row  = blockIdx.x * 8 + warp;   // 2S rows
    const float* src;
    float* dst;
    if (row < Ss) { src = sf1 + (size_t)row * Cc;        dst = g_sn1 + (size_t)row * Cc; }
    else          { src = sf2 + (size_t)(row - Ss) * Cc; dst = g_sn2 + (size_t)(row - Ss) * Cc; }

    float v[8];
    float sum = 0.f;
    #pragma unroll
    for (int k = 0; k < 8; k++) {
        v[k] = src[lane + 32 * k];
        sum += v[k] * v[k];
    }
    #pragma unroll
    for (int o = 16; o; o >>= 1) sum += __shfl_xor_sync(0xffffffffu, sum, o);
    float inv = 1.f / fmaxf(sqrtf(sum), EPSN);
    #pragma unroll
    for (int k = 0; k < 8; k++) dst[lane + 32 * k] = v[k] * inv;
}

// ---------------------------------------------------------------------------
// Kernel 2: fused dual-space scoring.
// Block = 512 thr = 8 teams x 64. team = (space sp, channel-quarter q).
// Thread owns 4 adjacent columns (one LDG.128 per channel), 8 sentences.
// Video feats read exactly once from HBM. Partials reduced via a 2-level
// smem tree (quarters->halves->full); team (0,0) runs the fused epilogue.
// grid = (4096/256, Bv) = (16,16).
// ---------------------------------------------------------------------------
__global__ __launch_bounds__(TPB, 2) void score_kernel(
    const float* __restrict__ vf1,
    const float* __restrict__ vf2,
    const float* __restrict__ mask2d,
    float* __restrict__ out) {

    // 36 KB shared, two aliased uses:
    //  - stage: duplicated sentence pairs, idx (spp*256+c)*8+s, 4096 ull
    //  - reduce scratch: slots of 18 ull per (team,thread)
    __shared__ ull buf[4608];

    const int tid  = threadIdx.x;
    const int team = tid >> 6;       // 0..7
    const int ttid = tid & 63;
    const int sp   = team >> 2;      // feature space
    const int q    = team & 3;       // channel quarter
    const int b    = blockIdx.y;
    const int ij0  = blockIdx.x * 256 + 4 * ttid;

    const int start = g_off[b];
    int end = g_off[b + 1];
    if (end > Ss) end = Ss;
    if (start >= end) return;        // uniform per block

    const float* vf = (sp == 0) ? vf1 : vf2;
    const ulonglong2* __restrict__ v = reinterpret_cast<const ulonglong2*>(
        vf + ((size_t)b * Cc + (size_t)q * 64) * NN + ij0);

    const ull* __restrict__ sb = buf + (size_t)(sp * 256 + q * 64) * 8;

    for (int cs = start; cs < end; cs += 8) {
        const int cnt = min(8, end - cs);

        // Stage duplicated sentence scalars (all 512 threads, 4096 ull)
        for (int e = tid; e < 2 * Cc * 8; e += TPB) {
            const int s   = e & 7;
            const int c   = (e >> 3) & (Cc - 1);
            const int spp = e >> 11;
            float val = 0.f;
            if (s < cnt)
                val = (spp == 0 ? g_sn1 : g_sn2)[(size_t)(cs + s) * Cc + c];
            float2 d = make_float2(val, val);
            buf[e] = *reinterpret_cast<ull*>(&d);
        }
        __syncthreads();

        ull accL[8], accH[8];           // lanes = {col0,col1} / {col2,col3}
        #pragma unroll
        for (int s = 0; s < 8; s++) { accL[s] = 0ull; accH[s] = 0ull; }
        ull nrmL = 0ull, nrmH = 0ull;

        #pragma unroll 4
        for (int k = 0; k < 64; k++) {
            const ulonglong2 a = v[(size_t)k * (NN / 4)];
            FFMA2(nrmL, a.x, a.x);
            FFMA2(nrmH, a.y, a.y);
            const ulonglong2* p =
                reinterpret_cast<const ulonglong2*>(sb + k * 8);
            const ulonglong2 q0 = p[0];
            const ulonglong2 q1 = p[1];
            const ulonglong2 q2 = p[2];
            const ulonglong2 q3 = p[3];
            FFMA2(accL[0], a.x, q0.x); FFMA2(accH[0], a.y, q0.x);
            FFMA2(accL[1], a.x, q0.y); FFMA2(accH[1], a.y, q0.y);
            FFMA2(accL[2], a.x, q1.x); FFMA2(accH[2], a.y, q1.x);
            FFMA2(accL[3], a.x, q1.y); FFMA2(accH[3], a.y, q1.y);
            FFMA2(accL[4], a.x, q2.x); FFMA2(accH[4], a.y, q2.x);
            FFMA2(accL[5], a.x, q2.y); FFMA2(accH[5], a.y, q2.y);
            FFMA2(accL[6], a.x, q3.x); FFMA2(accH[6], a.y, q3.x);
            FFMA2(accL[7], a.x, q3.y); FFMA2(accH[7], a.y, q3.y);
        }
        __syncthreads();   // done reading stage area

        // ---- Reduction tree over channel quarters ----
        // P1: quarters 2,3 publish
        if (q >= 2) {
            ull* w = buf + ((size_t)((sp * 2 + (q - 2)) * 64 + ttid)) * 18;
            #pragma unroll
            for (int s = 0; s < 8; s++) { w[s] = accL[s]; w[8 + s] = accH[s]; }
            w[16] = nrmL; w[17] = nrmH;
        }
        __syncthreads();
        if (q < 2) {
            const ull* r = buf + ((size_t)((sp * 2 + q) * 64 + ttid)) * 18;
            #pragma unroll
            for (int s = 0; s < 8; s++) {
                FADD2(accL[s], accL[s], r[s]);
                FADD2(accH[s], accH[s], r[8 + s]);
            }
            FADD2(nrmL, nrmL, r[16]);
            FADD2(nrmH, nrmH, r[17]);
        }
        __syncthreads();
        // P2: quarter 1 publishes half-sums
        if (q == 1) {
            ull* w = buf + ((size_t)(sp * 64 + ttid)) * 18;
            #pragma unroll
            for (int s = 0; s < 8; s++) { w[s] = accL[s]; w[8 + s] = accH[s]; }
            w[16] = nrmL; w[17] = nrmH;
        }
        __syncthreads();
        if (q == 0) {
            const ull* r = buf + ((size_t)(sp * 64 + ttid)) * 18;
            #pragma unroll
            for (int s = 0; s < 8; s++) {
                FADD2(accL[s], accL[s], r[s]);
                FADD2(accH[s], accH[s], r[8 + s]);
            }
            FADD2(nrmL, nrmL, r[16]);
            FADD2(nrmH, nrmH, r[17]);
            // P3: space-2 full sums -> slots (128+ttid)
            if (sp == 1) {
                ull* w = buf + ((size_t)(128 + ttid)) * 18;
                #pragma unroll
                for (int s = 0; s < 8; s++) { w[s] = accL[s]; w[8 + s] = accH[s]; }
                w[16] = nrmL; w[17] = nrmH;
            }
        }
        __syncthreads();

        // ---- Fused epilogue: team (0,0) only ----
        if (team == 0) {
            const ull* r2 = buf + ((size_t)(128 + ttid)) * 18;

            const float i1[4] = {
                1.f / fmaxf(sqrtf(f2lo(nrmL)), EPSN),
                1.f / fmaxf(sqrtf(f2hi(nrmL)), EPSN),
                1.f / fmaxf(sqrtf(f2lo(nrmH)), EPSN),
                1.f / fmaxf(sqrtf(f2hi(nrmH)), EPSN)
            };
            const ull n2L = r2[16], n2H = r2[17];
            const float i2[4] = {
                1.f / fmaxf(sqrtf(f2lo(n2L)), EPSN),
                1.f / fmaxf(sqrtf(f2hi(n2L)), EPSN),
                1.f / fmaxf(sqrtf(f2lo(n2H)), EPSN),
                1.f / fmaxf(sqrtf(f2hi(n2H)), EPSN)
            };
            const float4 mv = *reinterpret_cast<const float4*>(mask2d + ij0);
            const float m[4] = { mv.x, mv.y, mv.z, mv.w };

            for (int s = 0; s < cnt; s++) {
                const size_t srow = (size_t)(cs + s);
                const float d1[4] = { f2lo(accL[s]), f2hi(accL[s]),
                                      f2lo(accH[s]), f2hi(accH[s]) };
                const float d2[4] = { f2lo(r2[s]),     f2hi(r2[s]),
                                      f2lo(r2[8 + s]), f2hi(r2[8 + s]) };
                float4 o1, o2;
                float lg[4], sc[4];
                #pragma unroll
                for (int c = 0; c < 4; c++) {
                    lg[c] = SCALE * (d1[c] * i1[c]);
                    const float iou = m[c] / (1.f + __expf(-lg[c]));
                    const float con =
                        fmaxf((d2[c] * i2[c] + 1.f) * 0.5f * m[c], 0.f);
                    sc[c] = sqrtf(con) * iou;
                }
                o1 = make_float4(lg[0], lg[1], lg[2], lg[3]);
                o2 = make_float4(sc[0], sc[1], sc[2], sc[3]);
                *reinterpret_cast<float4*>(out + srow * NN + ij0) = o1;
                *reinterpret_cast<float4*>(
                    out + (size_t)Ss * NN + srow * NN + ij0) = o2;
            }
        }
        __syncthreads();   // smem safe to restage
    }
}

// ---------------------------------------------------------------------------
extern "C" void kernel_launch(void* const* d_in, const int* in_sizes, int n_in,
                              void* d_out, int out_size) {
    const float* vf1  = (const float*)d_in[0];
    const float* vf2  = (const float*)d_in[1];
    const float* sf1  = (const float*)d_in[2];
    const float* sf2  = (const float*)d_in[3];
    const float* mask = (const float*)d_in[4];
    const int*   nums = (const int*)d_in[5];
    float* out = (float*)d_out;

    prep_kernel<<<(2 * Ss) / 8, 256>>>(sf1, sf2, nums);
    score_kernel<<<dim3(NN / 256, Bv), TPB>>>(vf1, vf2, mask, out);
}